// round 1
// baseline (speedup 1.0000x reference)
#include <cuda_runtime.h>
#include <cuda_bf16.h>

// out = x > 0 ? 0.9*x + 0.1*tanh(x) : 0.5*tanh(x)
// Elementwise over 8192*8192 fp32. Pure HBM-streaming kernel.

__device__ __forceinline__ float act(float x) {
    float t = tanhf(x);
    return (x > 0.0f) ? fmaf(x, 0.9f, t * 0.1f) : (t * 0.5f);
}

__global__ void __launch_bounds__(256)
activation_vec4_kernel(const float4* __restrict__ in, float4* __restrict__ out, int n4) {
    int i = blockIdx.x * blockDim.x + threadIdx.x;
    if (i < n4) {
        float4 v = in[i];
        float4 r;
        r.x = act(v.x);
        r.y = act(v.y);
        r.z = act(v.z);
        r.w = act(v.w);
        out[i] = r;
    }
}

__global__ void __launch_bounds__(256)
activation_tail_kernel(const float* __restrict__ in, float* __restrict__ out,
                       int start, int n) {
    int i = start + blockIdx.x * blockDim.x + threadIdx.x;
    if (i < n) out[i] = act(in[i]);
}

extern "C" void kernel_launch(void* const* d_in, const int* in_sizes, int n_in,
                              void* d_out, int out_size) {
    const float* x = (const float*)d_in[0];
    float* out = (float*)d_out;
    int n = in_sizes[0];

    int n4 = n / 4;
    if (n4 > 0) {
        int threads = 256;
        int blocks = (n4 + threads - 1) / threads;
        activation_vec4_kernel<<<blocks, threads>>>(
            (const float4*)x, (float4*)out, n4);
    }
    int rem = n - n4 * 4;
    if (rem > 0) {
        activation_tail_kernel<<<1, 256>>>(x, out, n4 * 4, n);
    }
}

// round 2
// speedup vs baseline: 1.0300x; 1.0300x over previous
#include <cuda_runtime.h>
#include <cuda_bf16.h>

// out = x > 0 ? 0.9*x + 0.1*tanh(x) : 0.5*tanh(x)
// Elementwise over 8192*8192 fp32. Pure HBM-streaming kernel.
//
// R2: 4 float4 per thread, front-batched loads (MLP=4), streaming cache
// hints (__ldcs/__stcs) to avoid L2 pollution on a touch-once 512MB stream.

__device__ __forceinline__ float act(float x) {
    float t = tanhf(x);
    return (x > 0.0f) ? fmaf(x, 0.9f, t * 0.1f) : (t * 0.5f);
}

__device__ __forceinline__ float4 act4(float4 v) {
    float4 r;
    r.x = act(v.x);
    r.y = act(v.y);
    r.z = act(v.z);
    r.w = act(v.w);
    return r;
}

// Fast path: n4 exactly divisible by 4*total_threads partitioning.
// Each thread does 4 independent LDG.128 up front.
__global__ void __launch_bounds__(256)
activation_vec4x4_kernel(const float4* __restrict__ in, float4* __restrict__ out,
                         int stride /* = total threads = n4/4 */) {
    int i = blockIdx.x * blockDim.x + threadIdx.x;
    // Front-batched independent loads (streaming hint: evict-first)
    float4 v0 = __ldcs(&in[i]);
    float4 v1 = __ldcs(&in[i + stride]);
    float4 v2 = __ldcs(&in[i + 2 * stride]);
    float4 v3 = __ldcs(&in[i + 3 * stride]);

    __stcs(&out[i],              act4(v0));
    __stcs(&out[i + stride],     act4(v1));
    __stcs(&out[i + 2 * stride], act4(v2));
    __stcs(&out[i + 3 * stride], act4(v3));
}

// Generic path (bounds-checked grid-stride), used when shapes don't divide.
__global__ void __launch_bounds__(256)
activation_vec4_kernel(const float4* __restrict__ in, float4* __restrict__ out, int n4) {
    int i = blockIdx.x * blockDim.x + threadIdx.x;
    int stride = gridDim.x * blockDim.x;
    for (; i < n4; i += stride) {
        __stcs(&out[i], act4(__ldcs(&in[i])));
    }
}

__global__ void __launch_bounds__(256)
activation_tail_kernel(const float* __restrict__ in, float* __restrict__ out,
                       int start, int n) {
    int i = start + blockIdx.x * blockDim.x + threadIdx.x;
    if (i < n) out[i] = act(in[i]);
}

extern "C" void kernel_launch(void* const* d_in, const int* in_sizes, int n_in,
                              void* d_out, int out_size) {
    const float* x = (const float*)d_in[0];
    float* out = (float*)d_out;
    int n = in_sizes[0];

    const int threads = 256;
    int n4 = n / 4;

    if (n4 > 0 && (n4 % (4 * threads)) == 0) {
        // Fast path: n4 = 4 * total_threads, total_threads multiple of 256.
        int total_threads = n4 / 4;
        int blocks = total_threads / threads;
        activation_vec4x4_kernel<<<blocks, threads>>>(
            (const float4*)x, (float4*)out, total_threads);
    } else if (n4 > 0) {
        int blocks = (n4 + threads - 1) / threads;
        if (blocks > 65535 * 2) blocks = 65535 * 2;
        activation_vec4_kernel<<<blocks, threads>>>(
            (const float4*)x, (float4*)out, n4);
    }

    int rem = n - n4 * 4;
    if (rem > 0) {
        activation_tail_kernel<<<1, 256>>>(x, out, n4 * 4, n);
    }
}

// round 3
// speedup vs baseline: 1.0304x; 1.0004x over previous
#include <cuda_runtime.h>
#include <cuda_bf16.h>

// out = x > 0 ? 0.9*x + 0.1*tanh(x) : 0.5*tanh(x)
// Elementwise over 8192*8192 fp32. Pure HBM-streaming kernel.
//
// R2: 4 float4 per thread, front-batched loads (MLP=4), streaming cache
// hints (__ldcs/__stcs) to avoid L2 pollution on a touch-once 512MB stream.

__device__ __forceinline__ float act(float x) {
    float t = tanhf(x);
    return (x > 0.0f) ? fmaf(x, 0.9f, t * 0.1f) : (t * 0.5f);
}

__device__ __forceinline__ float4 act4(float4 v) {
    float4 r;
    r.x = act(v.x);
    r.y = act(v.y);
    r.z = act(v.z);
    r.w = act(v.w);
    return r;
}

// Fast path: n4 exactly divisible by 4*total_threads partitioning.
// Each thread does 4 independent LDG.128 up front.
__global__ void __launch_bounds__(256)
activation_vec4x4_kernel(const float4* __restrict__ in, float4* __restrict__ out,
                         int stride /* = total threads = n4/4 */) {
    int i = blockIdx.x * blockDim.x + threadIdx.x;
    // Front-batched independent loads (streaming hint: evict-first)
    float4 v0 = __ldcs(&in[i]);
    float4 v1 = __ldcs(&in[i + stride]);
    float4 v2 = __ldcs(&in[i + 2 * stride]);
    float4 v3 = __ldcs(&in[i + 3 * stride]);

    __stcs(&out[i],              act4(v0));
    __stcs(&out[i + stride],     act4(v1));
    __stcs(&out[i + 2 * stride], act4(v2));
    __stcs(&out[i + 3 * stride], act4(v3));
}

// Generic path (bounds-checked grid-stride), used when shapes don't divide.
__global__ void __launch_bounds__(256)
activation_vec4_kernel(const float4* __restrict__ in, float4* __restrict__ out, int n4) {
    int i = blockIdx.x * blockDim.x + threadIdx.x;
    int stride = gridDim.x * blockDim.x;
    for (; i < n4; i += stride) {
        __stcs(&out[i], act4(__ldcs(&in[i])));
    }
}

__global__ void __launch_bounds__(256)
activation_tail_kernel(const float* __restrict__ in, float* __restrict__ out,
                       int start, int n) {
    int i = start + blockIdx.x * blockDim.x + threadIdx.x;
    if (i < n) out[i] = act(in[i]);
}

extern "C" void kernel_launch(void* const* d_in, const int* in_sizes, int n_in,
                              void* d_out, int out_size) {
    const float* x = (const float*)d_in[0];
    float* out = (float*)d_out;
    int n = in_sizes[0];

    const int threads = 256;
    int n4 = n / 4;

    if (n4 > 0 && (n4 % (4 * threads)) == 0) {
        // Fast path: n4 = 4 * total_threads, total_threads multiple of 256.
        int total_threads = n4 / 4;
        int blocks = total_threads / threads;
        activation_vec4x4_kernel<<<blocks, threads>>>(
            (const float4*)x, (float4*)out, total_threads);
    } else if (n4 > 0) {
        int blocks = (n4 + threads - 1) / threads;
        if (blocks > 65535 * 2) blocks = 65535 * 2;
        activation_vec4_kernel<<<blocks, threads>>>(
            (const float4*)x, (float4*)out, n4);
    }

    int rem = n - n4 * 4;
    if (rem > 0) {
        activation_tail_kernel<<<1, 256>>>(x, out, n4 * 4, n);
    }
}